// round 5
// baseline (speedup 1.0000x reference)
#include <cuda_runtime.h>

#define N_NODES 50000
#define N_EDGES 1600000
#define BATCH   4
#define T_STEPS 50
#define DT      0.02f

#define NBLK   148
#define NTHR   1024
#define GROUPS (NTHR / 8)                               // 128 row-groups / block
#define ROWS_PER_BLK ((N_NODES + NBLK - 1) / NBLK)      // 338
#define NPASS  ((ROWS_PER_BLK + GROUPS - 1) / GROUPS)   // 3

// ---------------- static scratch (no allocations allowed) ----------------
__device__ int    g_hist[N_NODES];
__device__ int    g_row_start[N_NODES + 1];
__device__ int    g_cursor[N_NODES];
__device__ int2   g_edges[N_EDGES];       // (src_col, weight bits), CSR by target
__device__ float4 g_rates[2][N_NODES];    // ping-pong rate buffers
__device__ float  g_alpha[N_NODES];
__device__ unsigned          g_bar_count;
__device__ volatile unsigned g_bar_sense;

// ---------------- preprocessing ----------------

__global__ void init_kernel(const float* __restrict__ bias,
                            const float* __restrict__ tau) {
    int n = blockIdx.x * blockDim.x + threadIdx.x;
    if (n == 0) { g_bar_count = 0; g_bar_sense = 0; }
    if (n >= N_NODES) return;
    g_hist[n] = 0;
    float b = bias[n];
    float r = fmaxf(b, 0.0f);
    g_rates[0][n] = make_float4(r, r, r, r);
    float tt = fmaxf(tau[n], DT);
    g_alpha[n] = DT / tt;
}

__global__ void hist_kernel(const int* __restrict__ tgt) {
    int e = blockIdx.x * blockDim.x + threadIdx.x;
    if (e >= N_EDGES) return;
    atomicAdd(&g_hist[tgt[e]], 1);
}

__global__ void scan_kernel() {
    __shared__ int s[1024];
    int tid = threadIdx.x;
    const int chunk = (N_NODES + 1023) / 1024;
    int beg = tid * chunk;
    int end = min(beg + chunk, N_NODES);
    int sum = 0;
    for (int i = beg; i < end; i++) sum += g_hist[i];
    s[tid] = sum;
    __syncthreads();
    for (int off = 1; off < 1024; off <<= 1) {
        int v = (tid >= off) ? s[tid - off] : 0;
        __syncthreads();
        s[tid] += v;
        __syncthreads();
    }
    int prefix = (tid > 0) ? s[tid - 1] : 0;
    for (int i = beg; i < end; i++) {
        g_row_start[i] = prefix;
        g_cursor[i]    = prefix;
        prefix += g_hist[i];
    }
    if (tid == 0) g_row_start[N_NODES] = s[1023];
}

__global__ void scatter_kernel(const int*   __restrict__ src,
                               const int*   __restrict__ tgt,
                               const float* __restrict__ sign,
                               const float* __restrict__ cnt,
                               const float* __restrict__ str) {
    int e = blockIdx.x * blockDim.x + threadIdx.x;
    if (e >= N_EDGES) return;
    float w = sign[e] * fmaxf(cnt[e], 0.0f) * fmaxf(str[e], 0.0f);
    int pos = atomicAdd(&g_cursor[tgt[e]], 1);
    g_edges[pos] = make_int2(src[e], __float_as_int(w));
}

// ---------------- software grid barrier (all NBLK blocks resident) ------
__device__ __forceinline__ void grid_barrier(unsigned target) {
    __syncthreads();
    if (threadIdx.x == 0) {
        __threadfence();
        unsigned a = atomicAdd(&g_bar_count, 1);
        if (a == NBLK - 1) {
            g_bar_count = 0;
            __threadfence();
            g_bar_sense = target;
        } else {
            while (g_bar_sense != target) { }
            __threadfence();
        }
    }
    __syncthreads();
}

// ---------------- persistent kernel: all 50 steps in one launch ---------
// Each block owns ROWS_PER_BLK consecutive rows for the whole run:
//  - CSR edges for those rows become L1-resident after step 1
//  - membrane state v lives in registers (never touches memory)
//  - 8 lanes per row, 4-deep unrolled gather for MLP
__global__ void __launch_bounds__(NTHR, 1)
persist_kernel(const float* __restrict__ x,
               float*       __restrict__ out,
               const float* __restrict__ bias) {
    int sub = threadIdx.x & 7;
    int grp = threadIdx.x >> 3;
    int rowbase = blockIdx.x * ROWS_PER_BLK;
    int rowlim  = min(rowbase + ROWS_PER_BLK, N_NODES);

    // per-pass row metadata, loaded once
    int   beg[NPASS], end[NPASS], rowp[NPASS];
    float al[NPASS], bi[NPASS];
    float4 v[NPASS];
#pragma unroll
    for (int p = 0; p < NPASS; p++) {
        int row = rowbase + p * GROUPS + grp;
        bool ok = row < rowlim;
        rowp[p] = ok ? row : -1;
        beg[p]  = ok ? g_row_start[row]     : 0;
        end[p]  = ok ? g_row_start[row + 1] : 0;
        al[p]   = ok ? g_alpha[row] : 0.f;
        bi[p]   = ok ? bias[row]    : 0.f;
        v[p]    = make_float4(bi[p], bi[p], bi[p], bi[p]);  // v0 = bias
    }

    const long long TN = (long long)T_STEPS * N_NODES;

    for (int t = 0; t < T_STEPS; t++) {
        const float4* __restrict__ rin  = g_rates[t & 1];
        float4*       __restrict__ rout = g_rates[(t & 1) ^ 1];

#pragma unroll
        for (int p = 0; p < NPASS; p++) {
            float4 acc = make_float4(0.f, 0.f, 0.f, 0.f);
            for (int e0 = beg[p]; e0 < end[p]; e0 += 32) {
                int2 ed[4];
                bool pr[4];
#pragma unroll
                for (int j = 0; j < 4; j++) {
                    int ee = e0 + sub + 8 * j;
                    pr[j] = ee < end[p];
                    ed[j] = pr[j] ? g_edges[ee] : make_int2(0, 0);
                }
#pragma unroll
                for (int j = 0; j < 4; j++) {
                    if (pr[j]) {
                        float4 r = __ldg(&rin[ed[j].x]);
                        float  w = __int_as_float(ed[j].y);
                        acc.x = fmaf(w, r.x, acc.x);
                        acc.y = fmaf(w, r.y, acc.y);
                        acc.z = fmaf(w, r.z, acc.z);
                        acc.w = fmaf(w, r.w, acc.w);
                    }
                }
            }
            // reduce within 8-lane group (sub==0 ends with full sum)
#pragma unroll
            for (int off = 4; off; off >>= 1) {
                acc.x += __shfl_down_sync(0xffffffffu, acc.x, off);
                acc.y += __shfl_down_sync(0xffffffffu, acc.y, off);
                acc.z += __shfl_down_sync(0xffffffffu, acc.z, off);
                acc.w += __shfl_down_sync(0xffffffffu, acc.w, off);
            }
            if (sub == 0 && rowp[p] >= 0) {
                int row = rowp[p];
                long long base = (long long)t * N_NODES + row;
                float a = al[p], b = bi[p];
                float4 vn;
                vn.x = v[p].x + a * (b + acc.x + x[base         ] - v[p].x);
                vn.y = v[p].y + a * (b + acc.y + x[base +    TN ] - v[p].y);
                vn.z = v[p].z + a * (b + acc.z + x[base + 2*TN ] - v[p].z);
                vn.w = v[p].w + a * (b + acc.w + x[base + 3*TN ] - v[p].w);
                v[p] = vn;
                float4 r = make_float4(fmaxf(vn.x, 0.f), fmaxf(vn.y, 0.f),
                                       fmaxf(vn.z, 0.f), fmaxf(vn.w, 0.f));
                rout[row] = r;
                out[base         ] = r.x;
                out[base +    TN ] = r.y;
                out[base + 2*TN ] = r.z;
                out[base + 3*TN ] = r.w;
            }
        }
        if (t + 1 < T_STEPS) grid_barrier((unsigned)(t + 1));
    }
}

// ---------------- launch ----------------
extern "C" void kernel_launch(void* const* d_in, const int* in_sizes, int n_in,
                              void* d_out, int out_size) {
    const float* x    = (const float*)d_in[0];
    const float* bias = (const float*)d_in[1];
    const float* tau  = (const float*)d_in[2];
    const float* sign = (const float*)d_in[3];
    const float* cnt  = (const float*)d_in[4];
    const float* str  = (const float*)d_in[5];
    const int*   src  = (const int*)  d_in[6];
    const int*   tgt  = (const int*)  d_in[7];
    float*       out  = (float*)d_out;

    init_kernel<<<(N_NODES + 255) / 256, 256>>>(bias, tau);
    hist_kernel<<<(N_EDGES + 255) / 256, 256>>>(tgt);
    scan_kernel<<<1, 1024>>>();
    scatter_kernel<<<(N_EDGES + 255) / 256, 256>>>(src, tgt, sign, cnt, str);

    persist_kernel<<<NBLK, NTHR>>>(x, out, bias);
}